// round 1
// baseline (speedup 1.0000x reference)
#include <cuda_runtime.h>
#include <math.h>

// Problem constants (fixed by the dataset)
#define NN   100000
#define DIN  192
#define HH   64
#define DOUTT 32
#define CC   2
#define GG   256

// Scratch (static device arrays -- no allocation allowed)
__device__ float g_h  [NN * HH];   // current node features
__device__ float g_hw [NN * HH];   // h @ W (pre-aggregation)
__device__ float g_agg[NN * HH];   // aggregation accumulator
__device__ float g_dis[NN];        // degree, then deg^{-1/2}
__device__ float g_pool[GG * HH];  // per-graph feature sums
__device__ float g_cnt [GG];       // per-graph node counts

__device__ __forceinline__ void red_add_v4(float4* addr, float a, float b,
                                           float c, float d) {
    asm volatile("red.global.add.v4.f32 [%0], {%1, %2, %3, %4};"
                 :: "l"(addr), "f"(a), "f"(b), "f"(c), "f"(d)
                 : "memory");
}

// ---------------------------------------------------------------------------
__global__ void k_zero() {
    int i = blockIdx.x * blockDim.x + threadIdx.x;
    if (i < NN) g_dis[i] = 0.0f;
    if (i < GG * HH) g_pool[i] = 0.0f;
    if (i < GG) g_cnt[i] = 0.0f;
}

__global__ void k_degree(const int* __restrict__ src,
                         const int* __restrict__ dst, int E) {
    int i = blockIdx.x * blockDim.x + threadIdx.x;
    if (i >= E) return;
    atomicAdd(&g_dis[src[i]], 1.0f);
    atomicAdd(&g_dis[dst[i]], 1.0f);
}

__global__ void k_dis(int N) {
    int i = blockIdx.x * blockDim.x + threadIdx.x;
    if (i < N) g_dis[i] = rsqrtf(g_dis[i] + 1.0f);
}

// h = relu(x @ W_in + b_in).  Block = 256 threads = 4 nodes x 64 features.
__global__ void k_gemm_in(const float* __restrict__ x,
                          const float* __restrict__ W,
                          const float* __restrict__ b, int N) {
    __shared__ float Ws[64 * 64];
    __shared__ float xs[4 * 64];
    int f  = threadIdx.x & 63;
    int ln = threadIdx.x >> 6;          // local node 0..3
    int n  = blockIdx.x * 4 + ln;
    float acc = b[f];
    for (int kt = 0; kt < 3; kt++) {    // 3 k-tiles of 64 cover DIN=192
        for (int i = threadIdx.x; i < 64 * 64; i += 256)
            Ws[i] = W[(kt * 64 + (i >> 6)) * HH + (i & 63)];
        xs[ln * 64 + f] = (n < N) ? x[n * DIN + kt * 64 + f] : 0.0f;
        __syncthreads();
        #pragma unroll
        for (int k = 0; k < 64; k++)
            acc = fmaf(xs[ln * 64 + k], Ws[k * 64 + f], acc);
        __syncthreads();
    }
    if (n < N) g_h[n * HH + f] = fmaxf(acc, 0.0f);
}

// hw = h @ W ; agg = hw * dis^2  (self-loop term, also serves as init)
__global__ void k_gemm_h(const float* __restrict__ W, int N) {
    __shared__ float Ws[64 * 64];
    __shared__ float hs[4 * 64];
    int f  = threadIdx.x & 63;
    int ln = threadIdx.x >> 6;
    int n  = blockIdx.x * 4 + ln;
    for (int i = threadIdx.x; i < 64 * 64; i += 256) Ws[i] = W[i];
    hs[ln * 64 + f] = (n < N) ? g_h[n * HH + f] : 0.0f;
    __syncthreads();
    float acc = 0.0f;
    #pragma unroll
    for (int k = 0; k < 64; k++)
        acc = fmaf(hs[ln * 64 + k], Ws[k * 64 + f], acc);
    if (n < N) {
        g_hw[n * HH + f] = acc;
        float ds = g_dis[n];
        g_agg[n * HH + f] = acc * ds * ds;
    }
}

// Undirected message passing: 16 threads per edge, one float4 each direction.
__global__ void k_scatter(const int* __restrict__ src,
                          const int* __restrict__ dst, int E) {
    long tid = (long)blockIdx.x * blockDim.x + threadIdx.x;
    int e = (int)(tid >> 4);
    int q = (int)(tid & 15);
    if (e >= E) return;
    int s = src[e], d = dst[e];
    float c = g_dis[s] * g_dis[d];
    const float4* hw4 = (const float4*)g_hw;
    float4* agg4 = (float4*)g_agg;
    float4 hs = hw4[s * 16 + q];
    float4 hd = hw4[d * 16 + q];
    red_add_v4(&agg4[d * 16 + q], hs.x * c, hs.y * c, hs.z * c, hs.w * c);
    red_add_v4(&agg4[s * 16 + q], hd.x * c, hd.y * c, hd.z * c, hd.w * c);
}

// h = relu(agg + b)
__global__ void k_epilogue(const float* __restrict__ b, int N) {
    int i = blockIdx.x * blockDim.x + threadIdx.x;
    if (i >= N * HH) return;
    int f = i & 63;
    g_h[i] = fmaxf(g_agg[i] + b[f], 0.0f);
}

// Pooling: sums + counts via atomics
__global__ void k_pool(const int* __restrict__ batch, int N) {
    long tid = (long)blockIdx.x * blockDim.x + threadIdx.x;
    int n = (int)(tid >> 4);
    int q = (int)(tid & 15);
    if (n >= N) return;
    int g = batch[n];
    float4 v = ((const float4*)g_h)[n * 16 + q];
    red_add_v4(&((float4*)g_pool)[g * 16 + q], v.x, v.y, v.z, v.w);
    if (q == 0) atomicAdd(&g_cnt[g], 1.0f);
}

// Head: mean, FC(64->32)+relu, FC(32->2), log_softmax. One thread per graph.
__global__ void k_head(const float* __restrict__ Wf1,
                       const float* __restrict__ bf1,
                       const float* __restrict__ Wf2,
                       const float* __restrict__ bf2,
                       float* __restrict__ out) {
    __shared__ float W1s[HH * DOUTT];
    __shared__ float b1s[DOUTT];
    __shared__ float W2s[DOUTT * CC];
    __shared__ float b2s[CC];
    for (int i = threadIdx.x; i < HH * DOUTT; i += blockDim.x) W1s[i] = Wf1[i];
    if (threadIdx.x < DOUTT) b1s[threadIdx.x] = bf1[threadIdx.x];
    if (threadIdx.x < DOUTT * CC) W2s[threadIdx.x] = Wf2[threadIdx.x];
    if (threadIdx.x < CC) b2s[threadIdx.x] = bf2[threadIdx.x];
    __syncthreads();
    int g = threadIdx.x;
    if (g >= GG) return;
    float inv = 1.0f / fmaxf(g_cnt[g], 1.0f);
    float m[HH];
    #pragma unroll
    for (int k = 0; k < HH; k++) m[k] = g_pool[g * HH + k] * inv;
    float o0 = b2s[0], o1 = b2s[1];
    #pragma unroll
    for (int j = 0; j < DOUTT; j++) {
        float a = b1s[j];
        #pragma unroll
        for (int k = 0; k < HH; k++) a = fmaf(m[k], W1s[k * DOUTT + j], a);
        a = fmaxf(a, 0.0f);
        o0 = fmaf(a, W2s[j * CC + 0], o0);
        o1 = fmaf(a, W2s[j * CC + 1], o1);
    }
    float mx = fmaxf(o0, o1);
    float l = mx + logf(expf(o0 - mx) + expf(o1 - mx));
    out[g * CC + 0] = o0 - l;
    out[g * CC + 1] = o1 - l;
}

// ---------------------------------------------------------------------------
extern "C" void kernel_launch(void* const* d_in, const int* in_sizes, int n_in,
                              void* d_out, int out_size) {
    const float* x     = (const float*)d_in[0];
    const int*   ei    = (const int*)d_in[1];
    const int*   batch = (const int*)d_in[2];
    // num_graphs may appear as a scalar input at index 3 (size 1)
    int idx = (n_in >= 14 && in_sizes[3] == 1) ? 4 : 3;
    const float* W_in = (const float*)d_in[idx++];
    const float* b_in = (const float*)d_in[idx++];
    const float* W1   = (const float*)d_in[idx++];
    const float* b1   = (const float*)d_in[idx++];
    const float* W2   = (const float*)d_in[idx++];
    const float* b2   = (const float*)d_in[idx++];
    const float* Wf1  = (const float*)d_in[idx++];
    const float* bf1  = (const float*)d_in[idx++];
    const float* Wf2  = (const float*)d_in[idx++];
    const float* bf2  = (const float*)d_in[idx++];

    int N = in_sizes[0] / DIN;
    int E = in_sizes[1] / 2;
    const int* src = ei;
    const int* dst = ei + E;

    k_zero<<<(NN + 255) / 256, 256>>>();
    k_degree<<<(E + 255) / 256, 256>>>(src, dst, E);
    k_dis<<<(N + 255) / 256, 256>>>(N);

    k_gemm_in<<<(N + 3) / 4, 256>>>(x, W_in, b_in, N);

    // conv 1
    k_gemm_h<<<(N + 3) / 4, 256>>>(W1, N);
    k_scatter<<<(int)(((long)E * 16 + 255) / 256), 256>>>(src, dst, E);
    k_epilogue<<<(N * HH + 255) / 256, 256>>>(b1, N);

    // conv 2
    k_gemm_h<<<(N + 3) / 4, 256>>>(W2, N);
    k_scatter<<<(int)(((long)E * 16 + 255) / 256), 256>>>(src, dst, E);
    k_epilogue<<<(N * HH + 255) / 256, 256>>>(b2, N);

    k_pool<<<(int)(((long)N * 16 + 255) / 256), 256>>>(batch, N);
    k_head<<<1, 256>>>(Wf1, bf1, Wf2, bf2, (float*)d_out);
}

// round 3
// speedup vs baseline: 1.4767x; 1.4767x over previous
#include <cuda_runtime.h>
#include <math.h>

// Problem constants (fixed by the dataset)
#define NN    100000
#define E2MAX 3200000   // 2 * 1,600,000 directed edges
#define DIN   192
#define HH    64
#define DOUTT 32
#define CC    2
#define GG    256

// Scratch (static device arrays -- no allocation allowed)
__device__ __align__(16) float g_h  [NN * HH];   // node features
__device__ __align__(16) float g_hw [NN * HH];   // h @ W (pre-aggregation)
__device__ float g_dis[NN];          // deg^{-1/2}
__device__ int   g_deg[NN];          // degree (no self-loop)
__device__ int   g_rowstart[NN + 1]; // CSR row offsets
__device__ int   g_cursor[NN];       // fill cursors
__device__ int   g_adj[E2MAX];       // CSR adjacency (both directions)
__device__ __align__(16) float g_pool[GG * HH];
__device__ float g_cnt [GG];

__device__ __forceinline__ void red_add_v4(float4* addr, float a, float b,
                                           float c, float d) {
    asm volatile("red.global.add.v4.f32 [%0], {%1, %2, %3, %4};"
                 :: "l"(addr), "f"(a), "f"(b), "f"(c), "f"(d)
                 : "memory");
}

// ---------------------------------------------------------------------------
__global__ void k_init() {
    int i = blockIdx.x * blockDim.x + threadIdx.x;
    if (i < NN) g_deg[i] = 0;
    if (i < GG * HH) g_pool[i] = 0.0f;
    if (i < GG) g_cnt[i] = 0.0f;
}

__global__ void k_degree(const int* __restrict__ src,
                         const int* __restrict__ dst, int E) {
    int i = blockIdx.x * blockDim.x + threadIdx.x;
    if (i >= E) return;
    atomicAdd(&g_deg[src[i]], 1);
    atomicAdd(&g_deg[dst[i]], 1);
}

// Exclusive scan of degrees -> rowstart/cursor, plus dis.
// 1024 threads; per-thread chunk sums; thread 0 scans the 1024 partials
// serially (bulletproof, ~1us).
#define SCAN_T 1024
__global__ void k_scan(int N) {
    __shared__ int sums[SCAN_T];
    int t = threadIdx.x;
    int chunk = (N + SCAN_T - 1) / SCAN_T;
    int beg = t * chunk;
    int end = min(beg + chunk, N);
    int s = 0;
    for (int i = beg; i < end; i++) s += g_deg[i];
    sums[t] = s;
    __syncthreads();
    if (t == 0) {
        int run = 0;
        for (int u = 0; u < SCAN_T; u++) {
            int v = sums[u];
            sums[u] = run;       // exclusive prefix
            run += v;
        }
        g_rowstart[N] = run;     // total = 2E
    }
    __syncthreads();
    int run = sums[t];
    for (int i = beg; i < end; i++) {
        int d = g_deg[i];
        g_rowstart[i] = run;
        g_cursor[i]   = run;
        g_dis[i] = rsqrtf((float)d + 1.0f);
        run += d;
    }
}

__global__ void k_fill_adj(const int* __restrict__ src,
                           const int* __restrict__ dst, int E) {
    int i = blockIdx.x * blockDim.x + threadIdx.x;
    if (i >= E) return;
    int s = src[i], d = dst[i];
    int p0 = atomicAdd(&g_cursor[d], 1);
    g_adj[p0] = s;
    int p1 = atomicAdd(&g_cursor[s], 1);
    g_adj[p1] = d;
}

// ---------------------------------------------------------------------------
// Register-tiled SGEMM over fixed [*,64] weights.
// MODE 0: C=g_h  = relu(A @ W + bias)   (A = x, K=192)
// MODE 1: C=g_hw = g_h @ W              (K=64)
// Block tile 128x64, 128 threads, thread tile 8x8, BK=16.
// Device globals are referenced ONLY in device code (no symbol args).
template<int K, int MODE>
__global__ void k_gemm(const float* __restrict__ Aarg,
                       const float* __restrict__ W,
                       const float* __restrict__ bias, int N) {
    const float* A = (MODE == 0) ? Aarg : (const float*)g_h;
    float*       C = (MODE == 0) ? (float*)g_h : (float*)g_hw;

    __shared__ float  As[16][128];
    __shared__ float4 Ws4[16][16];   // Ws4[k][c] = W[kt+k][4c..4c+3]

    int t  = threadIdx.x;            // 0..127
    int tr = t >> 3;                 // 0..15 (row group)
    int tc = t & 7;                  // 0..7  (col group)
    int row0 = blockIdx.x * 128;

    float acc[8][8];
    #pragma unroll
    for (int i = 0; i < 8; i++)
        #pragma unroll
        for (int j = 0; j < 8; j++) acc[i][j] = 0.0f;

    for (int kt = 0; kt < K; kt += 16) {
        // A tile: each thread loads 16 consecutive k-values of one row,
        // stores transposed As[k][row].
        {
            int gr = row0 + t;
            float4 v0, v1, v2, v3;
            if (gr < N) {
                const float4* Ar = (const float4*)(A + (long)gr * K + kt);
                v0 = Ar[0]; v1 = Ar[1]; v2 = Ar[2]; v3 = Ar[3];
            } else {
                v0 = make_float4(0.f,0.f,0.f,0.f); v1 = v0; v2 = v0; v3 = v0;
            }
            As[ 0][t] = v0.x; As[ 1][t] = v0.y; As[ 2][t] = v0.z; As[ 3][t] = v0.w;
            As[ 4][t] = v1.x; As[ 5][t] = v1.y; As[ 6][t] = v1.z; As[ 7][t] = v1.w;
            As[ 8][t] = v2.x; As[ 9][t] = v2.y; As[10][t] = v2.z; As[11][t] = v2.w;
            As[12][t] = v3.x; As[13][t] = v3.y; As[14][t] = v3.z; As[15][t] = v3.w;
        }
        // W tile: 16x64 floats = 256 float4; linear copy.
        {
            const float4* Wg = (const float4*)(W + kt * 64);
            ((float4*)Ws4)[t]       = Wg[t];
            ((float4*)Ws4)[t + 128] = Wg[t + 128];
        }
        __syncthreads();
        #pragma unroll
        for (int k = 0; k < 16; k++) {
            float4 a0 = *(const float4*)&As[k][tr * 8];
            float4 a1 = *(const float4*)&As[k][tr * 8 + 4];
            float4 b0 = Ws4[k][tc * 2];
            float4 b1 = Ws4[k][tc * 2 + 1];
            float a[8], b[8];
            a[0]=a0.x; a[1]=a0.y; a[2]=a0.z; a[3]=a0.w;
            a[4]=a1.x; a[5]=a1.y; a[6]=a1.z; a[7]=a1.w;
            b[0]=b0.x; b[1]=b0.y; b[2]=b0.z; b[3]=b0.w;
            b[4]=b1.x; b[5]=b1.y; b[6]=b1.z; b[7]=b1.w;
            #pragma unroll
            for (int i = 0; i < 8; i++)
                #pragma unroll
                for (int j = 0; j < 8; j++)
                    acc[i][j] = fmaf(a[i], b[j], acc[i][j]);
        }
        __syncthreads();
    }

    // Epilogue
    float4 bb0 = make_float4(0.f,0.f,0.f,0.f), bb1 = bb0;
    if (MODE == 0) {
        bb0 = ((const float4*)bias)[tc * 2];
        bb1 = ((const float4*)bias)[tc * 2 + 1];
    }
    #pragma unroll
    for (int i = 0; i < 8; i++) {
        int gr = row0 + tr * 8 + i;
        if (gr < N) {
            float4 o0, o1;
            o0.x = acc[i][0]; o0.y = acc[i][1]; o0.z = acc[i][2]; o0.w = acc[i][3];
            o1.x = acc[i][4]; o1.y = acc[i][5]; o1.z = acc[i][6]; o1.w = acc[i][7];
            if (MODE == 0) {
                o0.x = fmaxf(o0.x + bb0.x, 0.f); o0.y = fmaxf(o0.y + bb0.y, 0.f);
                o0.z = fmaxf(o0.z + bb0.z, 0.f); o0.w = fmaxf(o0.w + bb0.w, 0.f);
                o1.x = fmaxf(o1.x + bb1.x, 0.f); o1.y = fmaxf(o1.y + bb1.y, 0.f);
                o1.z = fmaxf(o1.z + bb1.z, 0.f); o1.w = fmaxf(o1.w + bb1.w, 0.f);
            }
            float4* Cr = (float4*)(C + (long)gr * 64 + tc * 8);
            Cr[0] = o0;
            Cr[1] = o1;
        }
    }
}

// ---------------------------------------------------------------------------
// Pull-based aggregation: 16 lanes per node, accumulate neighbors in regs.
// g_h[n] = relu( sum_nbr g_hw[nbr]*dis[n]*dis[nbr] + g_hw[n]*dis[n]^2 + b )
__global__ void k_aggregate(const float* __restrict__ b, int N) {
    int n = blockIdx.x * 16 + (threadIdx.x >> 4);
    int q = threadIdx.x & 15;
    if (n >= N) return;
    float dn = g_dis[n];
    const float4* hw4 = (const float4*)g_hw;
    float4 acc = hw4[n * 16 + q];
    float dn2 = dn * dn;
    acc.x *= dn2; acc.y *= dn2; acc.z *= dn2; acc.w *= dn2;
    int s = g_rowstart[n];
    int e = g_rowstart[n + 1];
    for (int i = s; i < e; i++) {
        int nb = g_adj[i];
        float c = dn * g_dis[nb];
        float4 v = hw4[nb * 16 + q];
        acc.x = fmaf(v.x, c, acc.x);
        acc.y = fmaf(v.y, c, acc.y);
        acc.z = fmaf(v.z, c, acc.z);
        acc.w = fmaf(v.w, c, acc.w);
    }
    float4 bb = ((const float4*)b)[q];
    acc.x = fmaxf(acc.x + bb.x, 0.0f);
    acc.y = fmaxf(acc.y + bb.y, 0.0f);
    acc.z = fmaxf(acc.z + bb.z, 0.0f);
    acc.w = fmaxf(acc.w + bb.w, 0.0f);
    ((float4*)g_h)[n * 16 + q] = acc;
}

// ---------------------------------------------------------------------------
__global__ void k_pool(const int* __restrict__ batch, int N) {
    long tid = (long)blockIdx.x * blockDim.x + threadIdx.x;
    int n = (int)(tid >> 4);
    int q = (int)(tid & 15);
    if (n >= N) return;
    int g = batch[n];
    float4 v = ((const float4*)g_h)[n * 16 + q];
    red_add_v4(&((float4*)g_pool)[g * 16 + q], v.x, v.y, v.z, v.w);
    if (q == 0) atomicAdd(&g_cnt[g], 1.0f);
}

__global__ void k_head(const float* __restrict__ Wf1,
                       const float* __restrict__ bf1,
                       const float* __restrict__ Wf2,
                       const float* __restrict__ bf2,
                       float* __restrict__ out) {
    __shared__ float W1s[HH * DOUTT];
    __shared__ float b1s[DOUTT];
    __shared__ float W2s[DOUTT * CC];
    __shared__ float b2s[CC];
    for (int i = threadIdx.x; i < HH * DOUTT; i += blockDim.x) W1s[i] = Wf1[i];
    if (threadIdx.x < DOUTT) b1s[threadIdx.x] = bf1[threadIdx.x];
    if (threadIdx.x < DOUTT * CC) W2s[threadIdx.x] = Wf2[threadIdx.x];
    if (threadIdx.x < CC) b2s[threadIdx.x] = bf2[threadIdx.x];
    __syncthreads();
    int g = threadIdx.x;
    if (g >= GG) return;
    float inv = 1.0f / fmaxf(g_cnt[g], 1.0f);
    float m[HH];
    #pragma unroll
    for (int k = 0; k < HH; k++) m[k] = g_pool[g * HH + k] * inv;
    float o0 = b2s[0], o1 = b2s[1];
    #pragma unroll
    for (int j = 0; j < DOUTT; j++) {
        float a = b1s[j];
        #pragma unroll
        for (int k = 0; k < HH; k++) a = fmaf(m[k], W1s[k * DOUTT + j], a);
        a = fmaxf(a, 0.0f);
        o0 = fmaf(a, W2s[j * CC + 0], o0);
        o1 = fmaf(a, W2s[j * CC + 1], o1);
    }
    float mx = fmaxf(o0, o1);
    float l = mx + logf(expf(o0 - mx) + expf(o1 - mx));
    out[g * CC + 0] = o0 - l;
    out[g * CC + 1] = o1 - l;
}

// ---------------------------------------------------------------------------
extern "C" void kernel_launch(void* const* d_in, const int* in_sizes, int n_in,
                              void* d_out, int out_size) {
    const float* x     = (const float*)d_in[0];
    const int*   ei    = (const int*)d_in[1];
    const int*   batch = (const int*)d_in[2];
    int idx = (n_in >= 14 && in_sizes[3] == 1) ? 4 : 3;
    const float* W_in = (const float*)d_in[idx++];
    const float* b_in = (const float*)d_in[idx++];
    const float* W1   = (const float*)d_in[idx++];
    const float* b1   = (const float*)d_in[idx++];
    const float* W2   = (const float*)d_in[idx++];
    const float* b2   = (const float*)d_in[idx++];
    const float* Wf1  = (const float*)d_in[idx++];
    const float* bf1  = (const float*)d_in[idx++];
    const float* Wf2  = (const float*)d_in[idx++];
    const float* bf2  = (const float*)d_in[idx++];

    int N = in_sizes[0] / DIN;
    int E = in_sizes[1] / 2;
    const int* src = ei;
    const int* dst = ei + E;

    // CSR build (reused by both convs)
    k_init<<<(NN + 255) / 256, 256>>>();
    k_degree<<<(E + 255) / 256, 256>>>(src, dst, E);
    k_scan<<<1, SCAN_T>>>(N);
    k_fill_adj<<<(E + 255) / 256, 256>>>(src, dst, E);

    int gblocks = (N + 127) / 128;

    // h = relu(x @ W_in + b_in)
    k_gemm<DIN, 0><<<gblocks, 128>>>(x, W_in, b_in, N);

    // conv 1
    k_gemm<HH, 1><<<gblocks, 128>>>(nullptr, W1, nullptr, N);
    k_aggregate<<<(N + 15) / 16, 256>>>(b1, N);

    // conv 2
    k_gemm<HH, 1><<<gblocks, 128>>>(nullptr, W2, nullptr, N);
    k_aggregate<<<(N + 15) / 16, 256>>>(b2, N);

    // pooling + head
    k_pool<<<(int)(((long)N * 16 + 255) / 256), 256>>>(batch, N);
    k_head<<<1, 256>>>(Wf1, bf1, Wf2, bf2, (float*)d_out);
}

// round 4
// speedup vs baseline: 1.5193x; 1.0289x over previous
#include <cuda_runtime.h>
#include <math.h>

// Problem constants (fixed by the dataset)
#define NN    100000
#define E2MAX 3200000   // 2 * 1,600,000 directed edges
#define DIN   192
#define HH    64
#define DOUTT 32
#define CC    2
#define GG    256

// Scratch (static device arrays -- no allocation allowed)
__device__ __align__(16) float g_h  [NN * HH];   // node features
__device__ __align__(16) float g_hw [NN * HH];   // h @ W (pre-aggregation)
__device__ float g_dis[NN];          // deg^{-1/2}
__device__ int   g_deg[NN];          // degree (no self-loop)
__device__ int   g_rowstart[NN + 1]; // CSR row offsets
__device__ int   g_cursor[NN];       // fill cursors
__device__ __align__(16) int2 g_adjc[E2MAX]; // (neighbor, coef bits)
__device__ __align__(16) float g_pool[GG * HH];
__device__ float g_cnt [GG];

__device__ __forceinline__ void red_add_v4(float4* addr, float a, float b,
                                           float c, float d) {
    asm volatile("red.global.add.v4.f32 [%0], {%1, %2, %3, %4};"
                 :: "l"(addr), "f"(a), "f"(b), "f"(c), "f"(d)
                 : "memory");
}

// ---------------------------------------------------------------------------
__global__ void k_init() {
    int i = blockIdx.x * blockDim.x + threadIdx.x;
    if (i < NN) g_deg[i] = 0;
    if (i < GG * HH) g_pool[i] = 0.0f;
    if (i < GG) g_cnt[i] = 0.0f;
}

// Degree histogram, 4 edges per thread (8 independent atomics in flight).
__global__ void k_degree(const int* __restrict__ src,
                         const int* __restrict__ dst, int E) {
    int t = blockIdx.x * blockDim.x + threadIdx.x;
    int base = t * 4;
    if (base >= E) return;
    int s[4], d[4];
    int n;
    if (base + 4 <= E && (E & 3) == 0) {
        int4 s4 = *(const int4*)(src + base);
        int4 d4 = *(const int4*)(dst + base);
        s[0] = s4.x; s[1] = s4.y; s[2] = s4.z; s[3] = s4.w;
        d[0] = d4.x; d[1] = d4.y; d[2] = d4.z; d[3] = d4.w;
        n = 4;
    } else {
        n = min(4, E - base);
        for (int k = 0; k < n; k++) { s[k] = src[base + k]; d[k] = dst[base + k]; }
    }
    #pragma unroll
    for (int k = 0; k < 4; k++) {
        if (k < n) {
            atomicAdd(&g_deg[s[k]], 1);
            atomicAdd(&g_deg[d[k]], 1);
        }
    }
}

// Exclusive scan of degrees -> rowstart/cursor, plus dis.
#define SCAN_T 1024
__global__ void k_scan(int N) {
    __shared__ int sums[SCAN_T];
    int t = threadIdx.x;
    int chunk = (N + SCAN_T - 1) / SCAN_T;
    int beg = t * chunk;
    int end = min(beg + chunk, N);
    int s = 0;
    for (int i = beg; i < end; i++) s += g_deg[i];
    sums[t] = s;
    __syncthreads();
    if (t == 0) {
        int run = 0;
        for (int u = 0; u < SCAN_T; u++) {
            int v = sums[u];
            sums[u] = run;       // exclusive prefix
            run += v;
        }
        g_rowstart[N] = run;     // total = 2E
    }
    __syncthreads();
    int run = sums[t];
    for (int i = beg; i < end; i++) {
        int d = g_deg[i];
        g_rowstart[i] = run;
        g_cursor[i]   = run;
        g_dis[i] = rsqrtf((float)d + 1.0f);
        run += d;
    }
}

// CSR fill with per-entry coefficient, 4 edges per thread.
__global__ void k_fill_adj(const int* __restrict__ src,
                           const int* __restrict__ dst, int E) {
    int t = blockIdx.x * blockDim.x + threadIdx.x;
    int base = t * 4;
    if (base >= E) return;
    int s[4], d[4];
    int n;
    if (base + 4 <= E && (E & 3) == 0) {
        int4 s4 = *(const int4*)(src + base);
        int4 d4 = *(const int4*)(dst + base);
        s[0] = s4.x; s[1] = s4.y; s[2] = s4.z; s[3] = s4.w;
        d[0] = d4.x; d[1] = d4.y; d[2] = d4.z; d[3] = d4.w;
        n = 4;
    } else {
        n = min(4, E - base);
        for (int k = 0; k < n; k++) { s[k] = src[base + k]; d[k] = dst[base + k]; }
    }
    float cs[4];
    #pragma unroll
    for (int k = 0; k < 4; k++)
        if (k < n) cs[k] = g_dis[s[k]] * g_dis[d[k]];
    #pragma unroll
    for (int k = 0; k < 4; k++) {
        if (k < n) {
            int ci = __float_as_int(cs[k]);
            int p0 = atomicAdd(&g_cursor[d[k]], 1);
            g_adjc[p0] = make_int2(s[k], ci);
            int p1 = atomicAdd(&g_cursor[s[k]], 1);
            g_adjc[p1] = make_int2(d[k], ci);
        }
    }
}

// ---------------------------------------------------------------------------
// Fused: g_hw = relu(x @ W_in + b_in) @ W1.  (h never hits global memory.)
// Block tile 128 rows, 128 threads, 8x8 register tile, BK=16.
__global__ void k_gemm_fused(const float* __restrict__ x,
                             const float* __restrict__ W,
                             const float* __restrict__ bias,
                             const float* __restrict__ W1, int N) {
    __shared__ float As[16][128];
    __shared__ float Ws[16][64];
    __shared__ float Hs[64][128];   // transposed h tile: Hs[feat][row]
    int t  = threadIdx.x;
    int tr = t >> 3;                // 0..15
    int tc = t & 7;                 // 0..7
    int row0 = blockIdx.x * 128;

    float acc[8][8];
    #pragma unroll
    for (int i = 0; i < 8; i++)
        #pragma unroll
        for (int j = 0; j < 8; j++) acc[i][j] = 0.0f;

    // ---- GEMM 1: x[128 x 192] @ W_in[192 x 64] ----
    for (int kt = 0; kt < DIN; kt += 16) {
        {
            int gr = row0 + t;
            float4 v0, v1, v2, v3;
            if (gr < N) {
                const float4* Ar = (const float4*)(x + (long)gr * DIN + kt);
                v0 = Ar[0]; v1 = Ar[1]; v2 = Ar[2]; v3 = Ar[3];
            } else {
                v0 = make_float4(0.f,0.f,0.f,0.f); v1 = v0; v2 = v0; v3 = v0;
            }
            As[ 0][t] = v0.x; As[ 1][t] = v0.y; As[ 2][t] = v0.z; As[ 3][t] = v0.w;
            As[ 4][t] = v1.x; As[ 5][t] = v1.y; As[ 6][t] = v1.z; As[ 7][t] = v1.w;
            As[ 8][t] = v2.x; As[ 9][t] = v2.y; As[10][t] = v2.z; As[11][t] = v2.w;
            As[12][t] = v3.x; As[13][t] = v3.y; As[14][t] = v3.z; As[15][t] = v3.w;
        }
        {
            const float4* Wg = (const float4*)(W + kt * 64);
            ((float4*)Ws)[t]       = Wg[t];
            ((float4*)Ws)[t + 128] = Wg[t + 128];
        }
        __syncthreads();
        #pragma unroll
        for (int k = 0; k < 16; k++) {
            float4 a0 = *(const float4*)&As[k][tr * 8];
            float4 a1 = *(const float4*)&As[k][tr * 8 + 4];
            float4 b0 = *(const float4*)&Ws[k][tc * 8];
            float4 b1 = *(const float4*)&Ws[k][tc * 8 + 4];
            float a[8], b[8];
            a[0]=a0.x; a[1]=a0.y; a[2]=a0.z; a[3]=a0.w;
            a[4]=a1.x; a[5]=a1.y; a[6]=a1.z; a[7]=a1.w;
            b[0]=b0.x; b[1]=b0.y; b[2]=b0.z; b[3]=b0.w;
            b[4]=b1.x; b[5]=b1.y; b[6]=b1.z; b[7]=b1.w;
            #pragma unroll
            for (int i = 0; i < 8; i++)
                #pragma unroll
                for (int j = 0; j < 8; j++)
                    acc[i][j] = fmaf(a[i], b[j], acc[i][j]);
        }
        __syncthreads();
    }

    // Epilogue 1: h = relu(acc + bias), transposed into Hs[feat][row].
    {
        float4 bb0 = ((const float4*)bias)[tc * 2];
        float4 bb1 = ((const float4*)bias)[tc * 2 + 1];
        float bv[8];
        bv[0]=bb0.x; bv[1]=bb0.y; bv[2]=bb0.z; bv[3]=bb0.w;
        bv[4]=bb1.x; bv[5]=bb1.y; bv[6]=bb1.z; bv[7]=bb1.w;
        #pragma unroll
        for (int i = 0; i < 8; i++)
            #pragma unroll
            for (int j = 0; j < 8; j++)
                Hs[tc * 8 + j][tr * 8 + i] = fmaxf(acc[i][j] + bv[j], 0.0f);
    }
    __syncthreads();

    // ---- GEMM 2: h[128 x 64] @ W1[64 x 64] ----
    #pragma unroll
    for (int i = 0; i < 8; i++)
        #pragma unroll
        for (int j = 0; j < 8; j++) acc[i][j] = 0.0f;

    for (int kt = 0; kt < HH; kt += 16) {
        {
            const float4* Wg = (const float4*)(W1 + kt * 64);
            ((float4*)Ws)[t]       = Wg[t];
            ((float4*)Ws)[t + 128] = Wg[t + 128];
        }
        __syncthreads();
        #pragma unroll
        for (int k = 0; k < 16; k++) {
            float4 a0 = *(const float4*)&Hs[kt + k][tr * 8];
            float4 a1 = *(const float4*)&Hs[kt + k][tr * 8 + 4];
            float4 b0 = *(const float4*)&Ws[k][tc * 8];
            float4 b1 = *(const float4*)&Ws[k][tc * 8 + 4];
            float a[8], b[8];
            a[0]=a0.x; a[1]=a0.y; a[2]=a0.z; a[3]=a0.w;
            a[4]=a1.x; a[5]=a1.y; a[6]=a1.z; a[7]=a1.w;
            b[0]=b0.x; b[1]=b0.y; b[2]=b0.z; b[3]=b0.w;
            b[4]=b1.x; b[5]=b1.y; b[6]=b1.z; b[7]=b1.w;
            #pragma unroll
            for (int i = 0; i < 8; i++)
                #pragma unroll
                for (int j = 0; j < 8; j++)
                    acc[i][j] = fmaf(a[i], b[j], acc[i][j]);
        }
        __syncthreads();
    }

    #pragma unroll
    for (int i = 0; i < 8; i++) {
        int gr = row0 + tr * 8 + i;
        if (gr < N) {
            float4 o0, o1;
            o0.x = acc[i][0]; o0.y = acc[i][1]; o0.z = acc[i][2]; o0.w = acc[i][3];
            o1.x = acc[i][4]; o1.y = acc[i][5]; o1.z = acc[i][6]; o1.w = acc[i][7];
            float4* Cr = (float4*)(g_hw + (long)gr * 64 + tc * 8);
            Cr[0] = o0;
            Cr[1] = o1;
        }
    }
}

// g_hw = g_h @ W2 (64x64). Same register-tiled structure.
__global__ void k_gemm2(const float* __restrict__ W, int N) {
    __shared__ float As[16][128];
    __shared__ float Ws[16][64];
    int t  = threadIdx.x;
    int tr = t >> 3;
    int tc = t & 7;
    int row0 = blockIdx.x * 128;

    float acc[8][8];
    #pragma unroll
    for (int i = 0; i < 8; i++)
        #pragma unroll
        for (int j = 0; j < 8; j++) acc[i][j] = 0.0f;

    for (int kt = 0; kt < HH; kt += 16) {
        {
            int gr = row0 + t;
            float4 v0, v1, v2, v3;
            if (gr < N) {
                const float4* Ar = (const float4*)(g_h + (long)gr * HH + kt);
                v0 = Ar[0]; v1 = Ar[1]; v2 = Ar[2]; v3 = Ar[3];
            } else {
                v0 = make_float4(0.f,0.f,0.f,0.f); v1 = v0; v2 = v0; v3 = v0;
            }
            As[ 0][t] = v0.x; As[ 1][t] = v0.y; As[ 2][t] = v0.z; As[ 3][t] = v0.w;
            As[ 4][t] = v1.x; As[ 5][t] = v1.y; As[ 6][t] = v1.z; As[ 7][t] = v1.w;
            As[ 8][t] = v2.x; As[ 9][t] = v2.y; As[10][t] = v2.z; As[11][t] = v2.w;
            As[12][t] = v3.x; As[13][t] = v3.y; As[14][t] = v3.z; As[15][t] = v3.w;
        }
        {
            const float4* Wg = (const float4*)(W + kt * 64);
            ((float4*)Ws)[t]       = Wg[t];
            ((float4*)Ws)[t + 128] = Wg[t + 128];
        }
        __syncthreads();
        #pragma unroll
        for (int k = 0; k < 16; k++) {
            float4 a0 = *(const float4*)&As[k][tr * 8];
            float4 a1 = *(const float4*)&As[k][tr * 8 + 4];
            float4 b0 = *(const float4*)&Ws[k][tc * 8];
            float4 b1 = *(const float4*)&Ws[k][tc * 8 + 4];
            float a[8], b[8];
            a[0]=a0.x; a[1]=a0.y; a[2]=a0.z; a[3]=a0.w;
            a[4]=a1.x; a[5]=a1.y; a[6]=a1.z; a[7]=a1.w;
            b[0]=b0.x; b[1]=b0.y; b[2]=b0.z; b[3]=b0.w;
            b[4]=b1.x; b[5]=b1.y; b[6]=b1.z; b[7]=b1.w;
            #pragma unroll
            for (int i = 0; i < 8; i++)
                #pragma unroll
                for (int j = 0; j < 8; j++)
                    acc[i][j] = fmaf(a[i], b[j], acc[i][j]);
        }
        __syncthreads();
    }

    #pragma unroll
    for (int i = 0; i < 8; i++) {
        int gr = row0 + tr * 8 + i;
        if (gr < N) {
            float4 o0, o1;
            o0.x = acc[i][0]; o0.y = acc[i][1]; o0.z = acc[i][2]; o0.w = acc[i][3];
            o1.x = acc[i][4]; o1.y = acc[i][5]; o1.z = acc[i][6]; o1.w = acc[i][7];
            float4* Cr = (float4*)(g_hw + (long)gr * 64 + tc * 8);
            Cr[0] = o0;
            Cr[1] = o1;
        }
    }
}

// ---------------------------------------------------------------------------
// Pull-based aggregation, 16 lanes per node, unrolled x4 for MLP.
// POOL=false: g_h[n] = relu(agg + b)
// POOL=true : red_add relu(agg + b) into g_pool[batch[n]] (skip g_h).
template<bool POOL>
__global__ void k_aggregate(const float* __restrict__ b,
                            const int* __restrict__ batch, int N) {
    int n = blockIdx.x * 16 + (threadIdx.x >> 4);
    int q = threadIdx.x & 15;
    if (n >= N) return;
    const float4* hw4 = (const float4*)g_hw;
    float dn = g_dis[n];
    float4 acc = hw4[n * 16 + q];
    float dn2 = dn * dn;
    acc.x *= dn2; acc.y *= dn2; acc.z *= dn2; acc.w *= dn2;

    int s = g_rowstart[n];
    int e = g_rowstart[n + 1];
    int i = s;
    for (; i + 4 <= e; i += 4) {
        int2 a0 = g_adjc[i];
        int2 a1 = g_adjc[i + 1];
        int2 a2 = g_adjc[i + 2];
        int2 a3 = g_adjc[i + 3];
        float4 v0 = hw4[a0.x * 16 + q];
        float4 v1 = hw4[a1.x * 16 + q];
        float4 v2 = hw4[a2.x * 16 + q];
        float4 v3 = hw4[a3.x * 16 + q];
        float c0 = __int_as_float(a0.y);
        float c1 = __int_as_float(a1.y);
        float c2 = __int_as_float(a2.y);
        float c3 = __int_as_float(a3.y);
        acc.x = fmaf(v0.x, c0, acc.x); acc.y = fmaf(v0.y, c0, acc.y);
        acc.z = fmaf(v0.z, c0, acc.z); acc.w = fmaf(v0.w, c0, acc.w);
        acc.x = fmaf(v1.x, c1, acc.x); acc.y = fmaf(v1.y, c1, acc.y);
        acc.z = fmaf(v1.z, c1, acc.z); acc.w = fmaf(v1.w, c1, acc.w);
        acc.x = fmaf(v2.x, c2, acc.x); acc.y = fmaf(v2.y, c2, acc.y);
        acc.z = fmaf(v2.z, c2, acc.z); acc.w = fmaf(v2.w, c2, acc.w);
        acc.x = fmaf(v3.x, c3, acc.x); acc.y = fmaf(v3.y, c3, acc.y);
        acc.z = fmaf(v3.z, c3, acc.z); acc.w = fmaf(v3.w, c3, acc.w);
    }
    for (; i < e; i++) {
        int2 a0 = g_adjc[i];
        float4 v0 = hw4[a0.x * 16 + q];
        float c0 = __int_as_float(a0.y);
        acc.x = fmaf(v0.x, c0, acc.x); acc.y = fmaf(v0.y, c0, acc.y);
        acc.z = fmaf(v0.z, c0, acc.z); acc.w = fmaf(v0.w, c0, acc.w);
    }

    float4 bb = ((const float4*)b)[q];
    acc.x = fmaxf(acc.x + bb.x, 0.0f);
    acc.y = fmaxf(acc.y + bb.y, 0.0f);
    acc.z = fmaxf(acc.z + bb.z, 0.0f);
    acc.w = fmaxf(acc.w + bb.w, 0.0f);

    if (POOL) {
        int g = batch[n];
        red_add_v4(&((float4*)g_pool)[g * 16 + q], acc.x, acc.y, acc.z, acc.w);
        if (q == 0) atomicAdd(&g_cnt[g], 1.0f);
    } else {
        ((float4*)g_h)[n * 16 + q] = acc;
    }
}

// ---------------------------------------------------------------------------
__global__ void k_head(const float* __restrict__ Wf1,
                       const float* __restrict__ bf1,
                       const float* __restrict__ Wf2,
                       const float* __restrict__ bf2,
                       float* __restrict__ out) {
    __shared__ float W1s[HH * DOUTT];
    __shared__ float b1s[DOUTT];
    __shared__ float W2s[DOUTT * CC];
    __shared__ float b2s[CC];
    for (int i = threadIdx.x; i < HH * DOUTT; i += blockDim.x) W1s[i] = Wf1[i];
    if (threadIdx.x < DOUTT) b1s[threadIdx.x] = bf1[threadIdx.x];
    if (threadIdx.x < DOUTT * CC) W2s[threadIdx.x] = Wf2[threadIdx.x];
    if (threadIdx.x < CC) b2s[threadIdx.x] = bf2[threadIdx.x];
    __syncthreads();
    int g = threadIdx.x;
    if (g >= GG) return;
    float inv = 1.0f / fmaxf(g_cnt[g], 1.0f);
    float m[HH];
    #pragma unroll
    for (int k = 0; k < HH; k++) m[k] = g_pool[g * HH + k] * inv;
    float o0 = b2s[0], o1 = b2s[1];
    #pragma unroll
    for (int j = 0; j < DOUTT; j++) {
        float a = b1s[j];
        #pragma unroll
        for (int k = 0; k < HH; k++) a = fmaf(m[k], W1s[k * DOUTT + j], a);
        a = fmaxf(a, 0.0f);
        o0 = fmaf(a, W2s[j * CC + 0], o0);
        o1 = fmaf(a, W2s[j * CC + 1], o1);
    }
    float mx = fmaxf(o0, o1);
    float l = mx + logf(expf(o0 - mx) + expf(o1 - mx));
    out[g * CC + 0] = o0 - l;
    out[g * CC + 1] = o1 - l;
}

// ---------------------------------------------------------------------------
extern "C" void kernel_launch(void* const* d_in, const int* in_sizes, int n_in,
                              void* d_out, int out_size) {
    const float* x     = (const float*)d_in[0];
    const int*   ei    = (const int*)d_in[1];
    const int*   batch = (const int*)d_in[2];
    int idx = (n_in >= 14 && in_sizes[3] == 1) ? 4 : 3;
    const float* W_in = (const float*)d_in[idx++];
    const float* b_in = (const float*)d_in[idx++];
    const float* W1   = (const float*)d_in[idx++];
    const float* b1   = (const float*)d_in[idx++];
    const float* W2   = (const float*)d_in[idx++];
    const float* b2   = (const float*)d_in[idx++];
    const float* Wf1  = (const float*)d_in[idx++];
    const float* bf1  = (const float*)d_in[idx++];
    const float* Wf2  = (const float*)d_in[idx++];
    const float* bf2  = (const float*)d_in[idx++];

    int N = in_sizes[0] / DIN;
    int E = in_sizes[1] / 2;
    const int* src = ei;
    const int* dst = ei + E;

    int ethreads4 = (E + 3) / 4;

    // CSR build (reused by both convs)
    k_init<<<(NN + 255) / 256, 256>>>();
    k_degree<<<(ethreads4 + 255) / 256, 256>>>(src, dst, E);
    k_scan<<<1, SCAN_T>>>(N);
    k_fill_adj<<<(ethreads4 + 255) / 256, 256>>>(src, dst, E);

    int gblocks = (N + 127) / 128;

    // g_hw = relu(x @ W_in + b_in) @ W1   (fused; h stays on-chip)
    k_gemm_fused<<<gblocks, 128>>>(x, W_in, b_in, W1, N);
    // conv 1 aggregate -> g_h
    k_aggregate<false><<<(N + 15) / 16, 256>>>(b1, nullptr, N);

    // conv 2
    k_gemm2<<<gblocks, 128>>>(W2, N);
    // conv 2 aggregate fused with mean-pool accumulation
    k_aggregate<true><<<(N + 15) / 16, 256>>>(b2, batch, N);

    // head
    k_head<<<1, 256>>>(Wf1, bf1, Wf2, bf2, (float*)d_out);
}

// round 5
// speedup vs baseline: 1.5647x; 1.0299x over previous
#include <cuda_runtime.h>
#include <math.h>

// Problem constants (fixed by the dataset)
#define NN    100000
#define EMAX  1600000
#define E2MAX 3200000   // 2 * EMAX
#define DIN   192
#define HH    64
#define DOUTT 32
#define CC    2
#define GG    256

// Scratch (static device arrays -- no allocation allowed)
__device__ __align__(16) float g_h  [NN * HH];   // node features
__device__ __align__(16) float g_hw [NN * HH];   // h @ W (pre-aggregation)
__device__ float g_dis[NN];          // deg^{-1/2}
__device__ int   g_deg[NN];          // degree (no self-loop)
__device__ int   g_rowstart[NN + 1]; // CSR row offsets
__device__ __align__(16) int2 g_rank[EMAX];  // (rank in src list, rank in dst list)
__device__ __align__(16) int2 g_adjc[E2MAX]; // (neighbor, coef bits)
__device__ __align__(16) float g_pool[GG * HH];
__device__ float g_cnt [GG];

__device__ __forceinline__ void red_add_v4(float4* addr, float a, float b,
                                           float c, float d) {
    asm volatile("red.global.add.v4.f32 [%0], {%1, %2, %3, %4};"
                 :: "l"(addr), "f"(a), "f"(b), "f"(c), "f"(d)
                 : "memory");
}

// ---------------------------------------------------------------------------
__global__ void k_init() {
    int i = blockIdx.x * blockDim.x + threadIdx.x;
    if (i < NN) g_deg[i] = 0;
    if (i < GG * HH) g_pool[i] = 0.0f;
    if (i < GG) g_cnt[i] = 0.0f;
}

// Degree histogram; keep the returned rank so the fill pass needs no atomics.
__global__ void k_degree(const int* __restrict__ src,
                         const int* __restrict__ dst, int E) {
    int i = blockIdx.x * blockDim.x + threadIdx.x;
    if (i >= E) return;
    int s = src[i], d = dst[i];
    int rs = atomicAdd(&g_deg[s], 1);
    int rd = atomicAdd(&g_deg[d], 1);
    g_rank[i] = make_int2(rs, rd);
}

// Exclusive scan of degrees -> rowstart, plus dis.
#define SCAN_T 1024
__global__ void k_scan(int N) {
    __shared__ int sums[SCAN_T];
    int t = threadIdx.x;
    int chunk = (N + SCAN_T - 1) / SCAN_T;
    int beg = t * chunk;
    int end = min(beg + chunk, N);
    int s = 0;
    for (int i = beg; i < end; i++) s += g_deg[i];
    sums[t] = s;
    __syncthreads();
    if (t == 0) {
        int run = 0;
        for (int u = 0; u < SCAN_T; u++) {
            int v = sums[u];
            sums[u] = run;       // exclusive prefix
            run += v;
        }
        g_rowstart[N] = run;     // total = 2E
    }
    __syncthreads();
    int run = sums[t];
    for (int i = beg; i < end; i++) {
        int d = g_deg[i];
        g_rowstart[i] = run;
        g_dis[i] = rsqrtf((float)d + 1.0f);
        run += d;
    }
}

// CSR fill, atomic-free: slot = rowstart[node] + precomputed rank.
__global__ void k_fill_adj(const int* __restrict__ src,
                           const int* __restrict__ dst, int E) {
    int i = blockIdx.x * blockDim.x + threadIdx.x;
    if (i >= E) return;
    int s = src[i], d = dst[i];
    int2 r = g_rank[i];
    float c = g_dis[s] * g_dis[d];
    int ci = __float_as_int(c);
    g_adjc[g_rowstart[s] + r.x] = make_int2(d, ci);
    g_adjc[g_rowstart[d] + r.y] = make_int2(s, ci);
}

// ---------------------------------------------------------------------------
// Fused: g_hw = relu(x @ W_in + b_in) @ W1.  (h never hits global memory.)
// Block tile 128 rows, 128 threads, 8x8 register tile, BK=16.
__global__ void k_gemm_fused(const float* __restrict__ x,
                             const float* __restrict__ W,
                             const float* __restrict__ bias,
                             const float* __restrict__ W1, int N) {
    __shared__ float As[16][128];
    __shared__ float Ws[16][64];
    __shared__ float Hs[64][128];   // transposed h tile: Hs[feat][row]
    int t  = threadIdx.x;
    int tr = t >> 3;                // 0..15
    int tc = t & 7;                 // 0..7
    int row0 = blockIdx.x * 128;

    float acc[8][8];
    #pragma unroll
    for (int i = 0; i < 8; i++)
        #pragma unroll
        for (int j = 0; j < 8; j++) acc[i][j] = 0.0f;

    // ---- GEMM 1: x[128 x 192] @ W_in[192 x 64] ----
    for (int kt = 0; kt < DIN; kt += 16) {
        {
            int gr = row0 + t;
            float4 v0, v1, v2, v3;
            if (gr < N) {
                const float4* Ar = (const float4*)(x + (long)gr * DIN + kt);
                v0 = Ar[0]; v1 = Ar[1]; v2 = Ar[2]; v3 = Ar[3];
            } else {
                v0 = make_float4(0.f,0.f,0.f,0.f); v1 = v0; v2 = v0; v3 = v0;
            }
            As[ 0][t] = v0.x; As[ 1][t] = v0.y; As[ 2][t] = v0.z; As[ 3][t] = v0.w;
            As[ 4][t] = v1.x; As[ 5][t] = v1.y; As[ 6][t] = v1.z; As[ 7][t] = v1.w;
            As[ 8][t] = v2.x; As[ 9][t] = v2.y; As[10][t] = v2.z; As[11][t] = v2.w;
            As[12][t] = v3.x; As[13][t] = v3.y; As[14][t] = v3.z; As[15][t] = v3.w;
        }
        {
            const float4* Wg = (const float4*)(W + kt * 64);
            ((float4*)Ws)[t]       = Wg[t];
            ((float4*)Ws)[t + 128] = Wg[t + 128];
        }
        __syncthreads();
        #pragma unroll
        for (int k = 0; k < 16; k++) {
            float4 a0 = *(const float4*)&As[k][tr * 8];
            float4 a1 = *(const float4*)&As[k][tr * 8 + 4];
            float4 b0 = *(const float4*)&Ws[k][tc * 8];
            float4 b1 = *(const float4*)&Ws[k][tc * 8 + 4];
            float a[8], b[8];
            a[0]=a0.x; a[1]=a0.y; a[2]=a0.z; a[3]=a0.w;
            a[4]=a1.x; a[5]=a1.y; a[6]=a1.z; a[7]=a1.w;
            b[0]=b0.x; b[1]=b0.y; b[2]=b0.z; b[3]=b0.w;
            b[4]=b1.x; b[5]=b1.y; b[6]=b1.z; b[7]=b1.w;
            #pragma unroll
            for (int i = 0; i < 8; i++)
                #pragma unroll
                for (int j = 0; j < 8; j++)
                    acc[i][j] = fmaf(a[i], b[j], acc[i][j]);
        }
        __syncthreads();
    }

    // Epilogue 1: h = relu(acc + bias), transposed into Hs[feat][row].
    {
        float4 bb0 = ((const float4*)bias)[tc * 2];
        float4 bb1 = ((const float4*)bias)[tc * 2 + 1];
        float bv[8];
        bv[0]=bb0.x; bv[1]=bb0.y; bv[2]=bb0.z; bv[3]=bb0.w;
        bv[4]=bb1.x; bv[5]=bb1.y; bv[6]=bb1.z; bv[7]=bb1.w;
        #pragma unroll
        for (int i = 0; i < 8; i++)
            #pragma unroll
            for (int j = 0; j < 8; j++)
                Hs[tc * 8 + j][tr * 8 + i] = fmaxf(acc[i][j] + bv[j], 0.0f);
    }
    __syncthreads();

    // ---- GEMM 2: h[128 x 64] @ W1[64 x 64] ----
    #pragma unroll
    for (int i = 0; i < 8; i++)
        #pragma unroll
        for (int j = 0; j < 8; j++) acc[i][j] = 0.0f;

    for (int kt = 0; kt < HH; kt += 16) {
        {
            const float4* Wg = (const float4*)(W1 + kt * 64);
            ((float4*)Ws)[t]       = Wg[t];
            ((float4*)Ws)[t + 128] = Wg[t + 128];
        }
        __syncthreads();
        #pragma unroll
        for (int k = 0; k < 16; k++) {
            float4 a0 = *(const float4*)&Hs[kt + k][tr * 8];
            float4 a1 = *(const float4*)&Hs[kt + k][tr * 8 + 4];
            float4 b0 = *(const float4*)&Ws[k][tc * 8];
            float4 b1 = *(const float4*)&Ws[k][tc * 8 + 4];
            float a[8], b[8];
            a[0]=a0.x; a[1]=a0.y; a[2]=a0.z; a[3]=a0.w;
            a[4]=a1.x; a[5]=a1.y; a[6]=a1.z; a[7]=a1.w;
            b[0]=b0.x; b[1]=b0.y; b[2]=b0.z; b[3]=b0.w;
            b[4]=b1.x; b[5]=b1.y; b[6]=b1.z; b[7]=b1.w;
            #pragma unroll
            for (int i = 0; i < 8; i++)
                #pragma unroll
                for (int j = 0; j < 8; j++)
                    acc[i][j] = fmaf(a[i], b[j], acc[i][j]);
        }
        __syncthreads();
    }

    #pragma unroll
    for (int i = 0; i < 8; i++) {
        int gr = row0 + tr * 8 + i;
        if (gr < N) {
            float4 o0, o1;
            o0.x = acc[i][0]; o0.y = acc[i][1]; o0.z = acc[i][2]; o0.w = acc[i][3];
            o1.x = acc[i][4]; o1.y = acc[i][5]; o1.z = acc[i][6]; o1.w = acc[i][7];
            float4* Cr = (float4*)(g_hw + (long)gr * 64 + tc * 8);
            Cr[0] = o0;
            Cr[1] = o1;
        }
    }
}

// g_hw = g_h @ W2 (64x64). Same register-tiled structure.
__global__ void k_gemm2(const float* __restrict__ W, int N) {
    __shared__ float As[16][128];
    __shared__ float Ws[16][64];
    int t  = threadIdx.x;
    int tr = t >> 3;
    int tc = t & 7;
    int row0 = blockIdx.x * 128;

    float acc[8][8];
    #pragma unroll
    for (int i = 0; i < 8; i++)
        #pragma unroll
        for (int j = 0; j < 8; j++) acc[i][j] = 0.0f;

    for (int kt = 0; kt < HH; kt += 16) {
        {
            int gr = row0 + t;
            float4 v0, v1, v2, v3;
            if (gr < N) {
                const float4* Ar = (const float4*)(g_h + (long)gr * HH + kt);
                v0 = Ar[0]; v1 = Ar[1]; v2 = Ar[2]; v3 = Ar[3];
            } else {
                v0 = make_float4(0.f,0.f,0.f,0.f); v1 = v0; v2 = v0; v3 = v0;
            }
            As[ 0][t] = v0.x; As[ 1][t] = v0.y; As[ 2][t] = v0.z; As[ 3][t] = v0.w;
            As[ 4][t] = v1.x; As[ 5][t] = v1.y; As[ 6][t] = v1.z; As[ 7][t] = v1.w;
            As[ 8][t] = v2.x; As[ 9][t] = v2.y; As[10][t] = v2.z; As[11][t] = v2.w;
            As[12][t] = v3.x; As[13][t] = v3.y; As[14][t] = v3.z; As[15][t] = v3.w;
        }
        {
            const float4* Wg = (const float4*)(W + kt * 64);
            ((float4*)Ws)[t]       = Wg[t];
            ((float4*)Ws)[t + 128] = Wg[t + 128];
        }
        __syncthreads();
        #pragma unroll
        for (int k = 0; k < 16; k++) {
            float4 a0 = *(const float4*)&As[k][tr * 8];
            float4 a1 = *(const float4*)&As[k][tr * 8 + 4];
            float4 b0 = *(const float4*)&Ws[k][tc * 8];
            float4 b1 = *(const float4*)&Ws[k][tc * 8 + 4];
            float a[8], b[8];
            a[0]=a0.x; a[1]=a0.y; a[2]=a0.z; a[3]=a0.w;
            a[4]=a1.x; a[5]=a1.y; a[6]=a1.z; a[7]=a1.w;
            b[0]=b0.x; b[1]=b0.y; b[2]=b0.z; b[3]=b0.w;
            b[4]=b1.x; b[5]=b1.y; b[6]=b1.z; b[7]=b1.w;
            #pragma unroll
            for (int i = 0; i < 8; i++)
                #pragma unroll
                for (int j = 0; j < 8; j++)
                    acc[i][j] = fmaf(a[i], b[j], acc[i][j]);
        }
        __syncthreads();
    }

    #pragma unroll
    for (int i = 0; i < 8; i++) {
        int gr = row0 + tr * 8 + i;
        if (gr < N) {
            float4 o0, o1;
            o0.x = acc[i][0]; o0.y = acc[i][1]; o0.z = acc[i][2]; o0.w = acc[i][3];
            o1.x = acc[i][4]; o1.y = acc[i][5]; o1.z = acc[i][6]; o1.w = acc[i][7];
            float4* Cr = (float4*)(g_hw + (long)gr * 64 + tc * 8);
            Cr[0] = o0;
            Cr[1] = o1;
        }
    }
}

// ---------------------------------------------------------------------------
// Pull-based aggregation, 16 lanes per node, unrolled x8 for MLP.
// POOL=false: g_h[n] = relu(agg + b)
// POOL=true : red_add relu(agg + b) into g_pool[batch[n]] (skip g_h).
template<bool POOL>
__global__ void k_aggregate(const float* __restrict__ b,
                            const int* __restrict__ batch, int N) {
    int n = blockIdx.x * 16 + (threadIdx.x >> 4);
    int q = threadIdx.x & 15;
    if (n >= N) return;
    const float4* hw4 = (const float4*)g_hw;
    float dn = g_dis[n];
    float4 acc = hw4[n * 16 + q];
    float dn2 = dn * dn;
    acc.x *= dn2; acc.y *= dn2; acc.z *= dn2; acc.w *= dn2;

    int s = g_rowstart[n];
    int e = g_rowstart[n + 1];
    int i = s;
    for (; i + 8 <= e; i += 8) {
        int2 a0 = g_adjc[i];
        int2 a1 = g_adjc[i + 1];
        int2 a2 = g_adjc[i + 2];
        int2 a3 = g_adjc[i + 3];
        int2 a4 = g_adjc[i + 4];
        int2 a5 = g_adjc[i + 5];
        int2 a6 = g_adjc[i + 6];
        int2 a7 = g_adjc[i + 7];
        float4 v0 = hw4[a0.x * 16 + q];
        float4 v1 = hw4[a1.x * 16 + q];
        float4 v2 = hw4[a2.x * 16 + q];
        float4 v3 = hw4[a3.x * 16 + q];
        float4 v4 = hw4[a4.x * 16 + q];
        float4 v5 = hw4[a5.x * 16 + q];
        float4 v6 = hw4[a6.x * 16 + q];
        float4 v7 = hw4[a7.x * 16 + q];
        float c0 = __int_as_float(a0.y);
        float c1 = __int_as_float(a1.y);
        float c2 = __int_as_float(a2.y);
        float c3 = __int_as_float(a3.y);
        float c4 = __int_as_float(a4.y);
        float c5 = __int_as_float(a5.y);
        float c6 = __int_as_float(a6.y);
        float c7 = __int_as_float(a7.y);
        acc.x = fmaf(v0.x, c0, acc.x); acc.y = fmaf(v0.y, c0, acc.y);
        acc.z = fmaf(v0.z, c0, acc.z); acc.w = fmaf(v0.w, c0, acc.w);
        acc.x = fmaf(v1.x, c1, acc.x); acc.y = fmaf(v1.y, c1, acc.y);
        acc.z = fmaf(v1.z, c1, acc.z); acc.w = fmaf(v1.w, c1, acc.w);
        acc.x = fmaf(v2.x, c2, acc.x); acc.y = fmaf(v2.y, c2, acc.y);
        acc.z = fmaf(v2.z, c2, acc.z); acc.w = fmaf(v2.w, c2, acc.w);
        acc.x = fmaf(v3.x, c3, acc.x); acc.y = fmaf(v3.y, c3, acc.y);
        acc.z = fmaf(v3.z, c3, acc.z); acc.w = fmaf(v3.w, c3, acc.w);
        acc.x = fmaf(v4.x, c4, acc.x); acc.y = fmaf(v4.y, c4, acc.y);
        acc.z = fmaf(v4.z, c4, acc.z); acc.w = fmaf(v4.w, c4, acc.w);
        acc.x = fmaf(v5.x, c5, acc.x); acc.y = fmaf(v5.y, c5, acc.y);
        acc.z = fmaf(v5.z, c5, acc.z); acc.w = fmaf(v5.w, c5, acc.w);
        acc.x = fmaf(v6.x, c6, acc.x); acc.y = fmaf(v6.y, c6, acc.y);
        acc.z = fmaf(v6.z, c6, acc.z); acc.w = fmaf(v6.w, c6, acc.w);
        acc.x = fmaf(v7.x, c7, acc.x); acc.y = fmaf(v7.y, c7, acc.y);
        acc.z = fmaf(v7.z, c7, acc.z); acc.w = fmaf(v7.w, c7, acc.w);
    }
    for (; i < e; i++) {
        int2 a0 = g_adjc[i];
        float4 v0 = hw4[a0.x * 16 + q];
        float c0 = __int_as_float(a0.y);
        acc.x = fmaf(v0.x, c0, acc.x); acc.y = fmaf(v0.y, c0, acc.y);
        acc.z = fmaf(v0.z, c0, acc.z); acc.w = fmaf(v0.w, c0, acc.w);
    }

    float4 bb = ((const float4*)b)[q];
    acc.x = fmaxf(acc.x + bb.x, 0.0f);
    acc.y = fmaxf(acc.y + bb.y, 0.0f);
    acc.z = fmaxf(acc.z + bb.z, 0.0f);
    acc.w = fmaxf(acc.w + bb.w, 0.0f);

    if (POOL) {
        int g = batch[n];
        red_add_v4(&((float4*)g_pool)[g * 16 + q], acc.x, acc.y, acc.z, acc.w);
        if (q == 0) atomicAdd(&g_cnt[g], 1.0f);
    } else {
        ((float4*)g_h)[n * 16 + q] = acc;
    }
}

// ---------------------------------------------------------------------------
__global__ void k_head(const float* __restrict__ Wf1,
                       const float* __restrict__ bf1,
                       const float* __restrict__ Wf2,
                       const float* __restrict__ bf2,
                       float* __restrict__ out) {
    __shared__ float W1s[HH * DOUTT];
    __shared__ float b1s[DOUTT];
    __shared__ float W2s[DOUTT * CC];
    __shared__ float b2s[CC];
    for (int i = threadIdx.x; i < HH * DOUTT; i += blockDim.x) W1s[i] = Wf1[i];
    if (threadIdx.x < DOUTT) b1s[threadIdx.x] = bf1[threadIdx.x];
    if (threadIdx.x < DOUTT * CC) W2s[threadIdx.x] = Wf2[threadIdx.x];
    if (threadIdx.x < CC) b2s[threadIdx.x] = bf2[threadIdx.x];
    __syncthreads();
    int g = threadIdx.x;
    if (g >= GG) return;
    float inv = 1.0f / fmaxf(g_cnt[g], 1.0f);
    float m[HH];
    #pragma unroll
    for (int k = 0; k < HH; k++) m[k] = g_pool[g * HH + k] * inv;
    float o0 = b2s[0], o1 = b2s[1];
    #pragma unroll
    for (int j = 0; j < DOUTT; j++) {
        float a = b1s[j];
        #pragma unroll
        for (int k = 0; k < HH; k++) a = fmaf(m[k], W1s[k * DOUTT + j], a);
        a = fmaxf(a, 0.0f);
        o0 = fmaf(a, W2s[j * CC + 0], o0);
        o1 = fmaf(a, W2s[j * CC + 1], o1);
    }
    float mx = fmaxf(o0, o1);
    float l = mx + logf(expf(o0 - mx) + expf(o1 - mx));
    out[g * CC + 0] = o0 - l;
    out[g * CC + 1] = o1 - l;
}

// ---------------------------------------------------------------------------
extern "C" void kernel_launch(void* const* d_in, const int* in_sizes, int n_in,
                              void* d_out, int out_size) {
    const float* x     = (const float*)d_in[0];
    const int*   ei    = (const int*)d_in[1];
    const int*   batch = (const int*)d_in[2];
    int idx = (n_in >= 14 && in_sizes[3] == 1) ? 4 : 3;
    const float* W_in = (const float*)d_in[idx++];
    const float* b_in = (const float*)d_in[idx++];
    const float* W1   = (const float*)d_in[idx++];
    const float* b1   = (const float*)d_in[idx++];
    const float* W2   = (const float*)d_in[idx++];
    const float* b2   = (const float*)d_in[idx++];
    const float* Wf1  = (const float*)d_in[idx++];
    const float* bf1  = (const float*)d_in[idx++];
    const float* Wf2  = (const float*)d_in[idx++];
    const float* bf2  = (const float*)d_in[idx++];

    int N = in_sizes[0] / DIN;
    int E = in_sizes[1] / 2;
    const int* src = ei;
    const int* dst = ei + E;

    // One-time stream/event setup (host-side resources, created before the
    // first capture; the captured work per call is identical every time).
    static cudaStream_t sB = nullptr;
    static cudaEvent_t evFork = nullptr, evJoin = nullptr;
    if (sB == nullptr) {
        cudaStreamCreateWithFlags(&sB, cudaStreamNonBlocking);
        cudaEventCreateWithFlags(&evFork, cudaEventDisableTiming);
        cudaEventCreateWithFlags(&evJoin, cudaEventDisableTiming);
    }

    // Fork: CSR build on side stream, GEMM chain on main stream.
    cudaEventRecord(evFork, 0);
    cudaStreamWaitEvent(sB, evFork, 0);

    // --- side stream: CSR build ---
    k_init<<<(NN + 255) / 256, 256, 0, sB>>>();
    k_degree<<<(E + 255) / 256, 256, 0, sB>>>(src, dst, E);
    k_scan<<<1, SCAN_T, 0, sB>>>(N);
    k_fill_adj<<<(E + 255) / 256, 256, 0, sB>>>(src, dst, E);
    cudaEventRecord(evJoin, sB);

    int gblocks = (N + 127) / 128;

    // --- main stream: g_hw = relu(x @ W_in + b_in) @ W1 ---
    k_gemm_fused<<<gblocks, 128>>>(x, W_in, b_in, W1, N);

    // Join: aggregation needs both CSR and g_hw.
    cudaStreamWaitEvent(0, evJoin, 0);

    // conv 1 aggregate -> g_h
    k_aggregate<false><<<(N + 15) / 16, 256>>>(b1, nullptr, N);

    // conv 2
    k_gemm2<<<gblocks, 128>>>(W2, N);
    // conv 2 aggregate fused with mean-pool accumulation
    k_aggregate<true><<<(N + 15) / 16, 256>>>(b2, batch, N);

    // head
    k_head<<<1, 256>>>(Wf1, bf1, Wf2, bf2, (float*)d_out);
}